// round 2
// baseline (speedup 1.0000x reference)
#include <cuda_runtime.h>
#include <math.h>

#define NN 50000
#define EE 800000
#define CC 100000
#define DD 128

// ---------------- scratch (static device globals; no allocation) -------------
__device__ float g_agg[NN * DD];
__device__ float g_deg[NN];          // becomes invdeg after k_invdeg
__device__ float g_h0[NN * DD];
__device__ float g_h1[NN * DD];
__device__ float g_y[CC];
__device__ float g_pmax[256];
__device__ float g_MS[2];

// ---------------- utility ----------------------------------------------------
__global__ void k_zero4(float4* p, int n4) {
    int i = blockIdx.x * blockDim.x + threadIdx.x;
    int st = gridDim.x * blockDim.x;
    for (; i < n4; i += st) p[i] = make_float4(0.f, 0.f, 0.f, 0.f);
}

// ---------------- scatter-add of feature rows along edges --------------------
// one warp per edge; each lane handles 4 consecutive floats (float4 read, 4 REDs)
__global__ void k_scatter(const float* __restrict__ feat,
                          const int* __restrict__ src,
                          const int* __restrict__ dst,
                          float* __restrict__ agg,
                          float* __restrict__ deg,
                          int do_deg) {
    int gid = blockIdx.x * blockDim.x + threadIdx.x;
    int e = gid >> 5;
    int q = gid & 31;
    if (e >= EE) return;
    int s = __ldg(src + e);
    int d = __ldg(dst + e);
    if (do_deg && q == 0) atomicAdd(&deg[d], 1.0f);
    float4 v = *reinterpret_cast<const float4*>(feat + (size_t)s * DD + q * 4);
    float* a = agg + (size_t)d * DD + q * 4;
    atomicAdd(a + 0, v.x);
    atomicAdd(a + 1, v.y);
    atomicAdd(a + 2, v.z);
    atomicAdd(a + 3, v.w);
}

__global__ void k_invdeg() {
    int n = blockIdx.x * blockDim.x + threadIdx.x;
    if (n < NN) g_deg[n] = 1.0f / fmaxf(g_deg[n], 1.0f);
}

// ---------------- fused SAGE layer: [64 nodes x 128 out], K=256 --------------
// h = lrelu( s * (X@Ws + (AGG*invdeg)@Wn + b - rm) + beta ),  s = gamma*rsqrt(rv+eps)
__global__ __launch_bounds__(256) void k_sage(
    const float* __restrict__ X, const float* __restrict__ Wself,
    const float* __restrict__ Wneigh, const float* __restrict__ bias,
    const float* __restrict__ gamma, const float* __restrict__ beta,
    const float* __restrict__ rm, const float* __restrict__ rv,
    float* __restrict__ OUT) {
    __shared__ float As[16 * 68];    // [kk][node], padded
    __shared__ float Ws[16 * 128];   // [kk][j]

    int t = threadIdx.x;
    int tj = t & 31;          // j tile: j = tj*4 + jj
    int tn = t >> 5;          // node tile: n = tn*8 + i
    int base = blockIdx.x * 64;

    float4 acc[8];
#pragma unroll
    for (int i = 0; i < 8; i++) acc[i] = make_float4(0.f, 0.f, 0.f, 0.f);

    int kkA = t & 15, n0 = t >> 4;       // A-tile load mapping
    int jW = t & 127, kk0 = t >> 7;      // W-tile load mapping

    for (int kb = 0; kb < 256; kb += 16) {
        const bool selfPart = (kb < 128);
        const int koff = selfPart ? kb : kb - 128;
        const float* SRC = selfPart ? X : g_agg;
        const float* WSRC = selfPart ? Wself : Wneigh;
#pragma unroll
        for (int i = 0; i < 4; i++) {
            int n = n0 + 16 * i;
            int row = base + n;
            float v = 0.f;
            if (row < NN) {
                v = __ldg(SRC + (size_t)row * DD + koff + kkA);
                if (!selfPart) v *= g_deg[row];   // invdeg
            }
            As[kkA * 68 + n] = v;
        }
#pragma unroll
        for (int i = 0; i < 8; i++) {
            int kk = kk0 + 2 * i;
            Ws[kk * 128 + jW] = __ldg(WSRC + (size_t)(koff + kk) * DD + jW);
        }
        __syncthreads();
#pragma unroll
        for (int kk = 0; kk < 16; kk++) {
            float4 w = *reinterpret_cast<float4*>(Ws + kk * 128 + tj * 4);
            float4 a0 = *reinterpret_cast<float4*>(As + kk * 68 + tn * 8);
            float4 a1 = *reinterpret_cast<float4*>(As + kk * 68 + tn * 8 + 4);
            float av[8] = {a0.x, a0.y, a0.z, a0.w, a1.x, a1.y, a1.z, a1.w};
#pragma unroll
            for (int i = 0; i < 8; i++) {
                acc[i].x += av[i] * w.x;
                acc[i].y += av[i] * w.y;
                acc[i].z += av[i] * w.z;
                acc[i].w += av[i] * w.w;
            }
        }
        __syncthreads();
    }

    // folded BatchNorm + bias + leaky relu epilogue
    int j = tj * 4;
    float4 g = *reinterpret_cast<const float4*>(gamma + j);
    float4 rvv = *reinterpret_cast<const float4*>(rv + j);
    float4 bb = *reinterpret_cast<const float4*>(bias + j);
    float4 rmm = *reinterpret_cast<const float4*>(rm + j);
    float4 be = *reinterpret_cast<const float4*>(beta + j);
    float4 s, sh;
    s.x = g.x * rsqrtf(rvv.x + 1e-5f);
    s.y = g.y * rsqrtf(rvv.y + 1e-5f);
    s.z = g.z * rsqrtf(rvv.z + 1e-5f);
    s.w = g.w * rsqrtf(rvv.w + 1e-5f);
    sh.x = s.x * (bb.x - rmm.x) + be.x;
    sh.y = s.y * (bb.y - rmm.y) + be.y;
    sh.z = s.z * (bb.z - rmm.z) + be.z;
    sh.w = s.w * (bb.w - rmm.w) + be.w;
#pragma unroll
    for (int i = 0; i < 8; i++) {
        int row = base + tn * 8 + i;
        if (row >= NN) continue;
        float4 v;
        v.x = s.x * acc[i].x + sh.x;
        v.y = s.y * acc[i].y + sh.y;
        v.z = s.z * acc[i].z + sh.z;
        v.w = s.w * acc[i].w + sh.w;
        v.x = v.x > 0.f ? v.x : 0.01f * v.x;
        v.y = v.y > 0.f ? v.y : 0.01f * v.y;
        v.z = v.z > 0.f ? v.z : 0.01f * v.z;
        v.w = v.w > 0.f ? v.w : 0.01f * v.w;
        *reinterpret_cast<float4*>(OUT + (size_t)row * DD + tj * 4) = v;
    }
}

// ---------------- candidate MLP: [64 cands] per block, 3 layers --------------
__global__ __launch_bounds__(128) void k_mlp(
    const int* __restrict__ cu, const int* __restrict__ cv,
    const float* __restrict__ cf,
    const float* __restrict__ mw0, const float* __restrict__ mb0,
    const float* __restrict__ mw1, const float* __restrict__ mb1,
    const float* __restrict__ mw2, const float* __restrict__ mb2) {
    extern __shared__ float sm[];
    float* Ce = sm;               // [257][68]  (k, cand)
    float* Z1 = sm + 257 * 68;    // [64][68]
    float* Z2 = Z1 + 64 * 68;     // [64][68]

    int t = threadIdx.x;
    int cbase = blockIdx.x * 64;
    int w = t >> 5, lane = t & 31;

    // build candidate embedding tile (transposed): Ce[k][c]
    for (int ci = 0; ci < 16; ci++) {
        int c = w * 16 + ci;
        int cg = cbase + c;
        int cgc = cg < CC ? cg : 0;
        int u = __ldg(cu + cgc);
        int v = __ldg(cv + cgc);
#pragma unroll
        for (int kk = 0; kk < 4; kk++) {
            int k = lane + kk * 32;
            Ce[k * 68 + c] = g_h1[(size_t)u * DD + k];
            Ce[(k + 128) * 68 + c] = g_h1[(size_t)v * DD + k];
        }
        if (lane == 0) Ce[256 * 68 + c] = __ldg(cf + cgc);
    }
    __syncthreads();

    int tj = t & 15;   // j = tj*4 + jj
    int tc = t >> 4;   // c = tc*8 + i
    float4 acc[8];
#pragma unroll
    for (int i = 0; i < 8; i++) acc[i] = make_float4(0.f, 0.f, 0.f, 0.f);

    // layer 0: K = 257
    for (int k = 0; k < 257; k++) {
        float4 wv = __ldg(reinterpret_cast<const float4*>(mw0 + k * 64 + tj * 4));
        float4 a0 = *reinterpret_cast<float4*>(Ce + k * 68 + tc * 8);
        float4 a1 = *reinterpret_cast<float4*>(Ce + k * 68 + tc * 8 + 4);
        float av[8] = {a0.x, a0.y, a0.z, a0.w, a1.x, a1.y, a1.z, a1.w};
#pragma unroll
        for (int i = 0; i < 8; i++) {
            acc[i].x += av[i] * wv.x;
            acc[i].y += av[i] * wv.y;
            acc[i].z += av[i] * wv.z;
            acc[i].w += av[i] * wv.w;
        }
    }
    {
        float4 bv = __ldg(reinterpret_cast<const float4*>(mb0 + tj * 4));
#pragma unroll
        for (int i = 0; i < 8; i++) {
            float vx = acc[i].x + bv.x; vx = vx > 0.f ? vx : 0.01f * vx;
            float vy = acc[i].y + bv.y; vy = vy > 0.f ? vy : 0.01f * vy;
            float vz = acc[i].z + bv.z; vz = vz > 0.f ? vz : 0.01f * vz;
            float vw = acc[i].w + bv.w; vw = vw > 0.f ? vw : 0.01f * vw;
            int c = tc * 8 + i;
            Z1[(tj * 4 + 0) * 68 + c] = vx;
            Z1[(tj * 4 + 1) * 68 + c] = vy;
            Z1[(tj * 4 + 2) * 68 + c] = vz;
            Z1[(tj * 4 + 3) * 68 + c] = vw;
        }
    }
    __syncthreads();

    // layer 1: K = 64
#pragma unroll
    for (int i = 0; i < 8; i++) acc[i] = make_float4(0.f, 0.f, 0.f, 0.f);
    for (int k = 0; k < 64; k++) {
        float4 wv = __ldg(reinterpret_cast<const float4*>(mw1 + k * 64 + tj * 4));
        float4 a0 = *reinterpret_cast<float4*>(Z1 + k * 68 + tc * 8);
        float4 a1 = *reinterpret_cast<float4*>(Z1 + k * 68 + tc * 8 + 4);
        float av[8] = {a0.x, a0.y, a0.z, a0.w, a1.x, a1.y, a1.z, a1.w};
#pragma unroll
        for (int i = 0; i < 8; i++) {
            acc[i].x += av[i] * wv.x;
            acc[i].y += av[i] * wv.y;
            acc[i].z += av[i] * wv.z;
            acc[i].w += av[i] * wv.w;
        }
    }
    {
        float4 bv = __ldg(reinterpret_cast<const float4*>(mb1 + tj * 4));
#pragma unroll
        for (int i = 0; i < 8; i++) {
            float vx = acc[i].x + bv.x; vx = vx > 0.f ? vx : 0.01f * vx;
            float vy = acc[i].y + bv.y; vy = vy > 0.f ? vy : 0.01f * vy;
            float vz = acc[i].z + bv.z; vz = vz > 0.f ? vz : 0.01f * vz;
            float vw = acc[i].w + bv.w; vw = vw > 0.f ? vw : 0.01f * vw;
            int c = tc * 8 + i;
            Z2[(tj * 4 + 0) * 68 + c] = vx;
            Z2[(tj * 4 + 1) * 68 + c] = vy;
            Z2[(tj * 4 + 2) * 68 + c] = vz;
            Z2[(tj * 4 + 3) * 68 + c] = vw;
        }
    }
    __syncthreads();

    // layer 2: y[c] = z2 . mw2 + mb2
    if (t < 64) {
        int c = t;
        float a = __ldg(mb2);
#pragma unroll 8
        for (int j = 0; j < 64; j++) a += Z2[j * 68 + c] * __ldg(mw2 + j);
        int cg = cbase + c;
        if (cg < CC) g_y[cg] = a;
    }
}

// ---------------- softmax over C ---------------------------------------------
__global__ void k_max_part() {
    __shared__ float s[256];
    int t = threadIdx.x;
    float m = -1e30f;
    for (int i = blockIdx.x * 256 + t; i < CC; i += 256 * 256) m = fmaxf(m, g_y[i]);
    s[t] = m;
    __syncthreads();
    for (int o = 128; o > 0; o >>= 1) {
        if (t < o) s[t] = fmaxf(s[t], s[t + o]);
        __syncthreads();
    }
    if (t == 0) g_pmax[blockIdx.x] = s[0];
}

__global__ void k_sumexp() {
    __shared__ float s[1024];
    int t = threadIdx.x;
    s[t] = (t < 256) ? g_pmax[t] : -1e30f;
    __syncthreads();
    for (int o = 512; o > 0; o >>= 1) {
        if (t < o) s[t] = fmaxf(s[t], s[t + o]);
        __syncthreads();
    }
    float M = s[0];
    __syncthreads();
    float sum = 0.f;
    for (int i = t; i < CC; i += 1024) sum += expf(g_y[i] - M);
    s[t] = sum;
    __syncthreads();
    for (int o = 512; o > 0; o >>= 1) {
        if (t < o) s[t] += s[t + o];
        __syncthreads();
    }
    if (t == 0) { g_MS[0] = M; g_MS[1] = s[0]; }
}

__global__ void k_writeout(float* __restrict__ out, int out_size) {
    int i = blockIdx.x * blockDim.x + threadIdx.x;
    if (i >= CC) return;
    float y = g_y[i];
    if (out_size >= CC) out[i] = y;
    if (out_size >= 2 * CC) out[CC + i] = expf(y - g_MS[0]) / g_MS[1];
}

// ---------------- launch -----------------------------------------------------
extern "C" void kernel_launch(void* const* d_in, const int* in_sizes, int n_in,
                              void* d_out, int out_size) {
    const float* x   = (const float*)d_in[0];
    const int*   src = (const int*)d_in[1];
    const int*   dst = (const int*)d_in[2];
    const int*   cu  = (const int*)d_in[3];
    const int*   cv  = (const int*)d_in[4];
    const float* cf  = (const float*)d_in[5];
    const float* ws0 = (const float*)d_in[6];
    const float* wn0 = (const float*)d_in[7];
    const float* b0  = (const float*)d_in[8];
    const float* g0  = (const float*)d_in[9];
    const float* be0 = (const float*)d_in[10];
    const float* rm0 = (const float*)d_in[11];
    const float* rv0 = (const float*)d_in[12];
    const float* ws1 = (const float*)d_in[13];
    const float* wn1 = (const float*)d_in[14];
    const float* b1  = (const float*)d_in[15];
    const float* g1  = (const float*)d_in[16];
    const float* be1 = (const float*)d_in[17];
    const float* rm1 = (const float*)d_in[18];
    const float* rv1 = (const float*)d_in[19];
    const float* mw0 = (const float*)d_in[20];
    const float* mb0 = (const float*)d_in[21];
    const float* mw1 = (const float*)d_in[22];
    const float* mb1 = (const float*)d_in[23];
    const float* mw2 = (const float*)d_in[24];
    const float* mb2 = (const float*)d_in[25];
    float* out = (float*)d_out;

    void *p_agg = nullptr, *p_deg = nullptr, *p_h0 = nullptr, *p_h1 = nullptr;
    cudaGetSymbolAddress(&p_agg, g_agg);
    cudaGetSymbolAddress(&p_deg, g_deg);
    cudaGetSymbolAddress(&p_h0, g_h0);
    cudaGetSymbolAddress(&p_h1, g_h1);

    static bool attr_set = false;
    if (!attr_set) {
        cudaFuncSetAttribute(k_mlp, cudaFuncAttributeMaxDynamicSharedMemorySize,
                             (257 + 64 + 64) * 68 * (int)sizeof(float));
        attr_set = true;
    }

    const int aggN4 = (NN * DD) / 4;
    const int scatterBlocks = (EE * 32 + 255) / 256;
    const int sageBlocks = (NN + 63) / 64;
    const int mlpBlocks = (CC + 63) / 64;
    const int mlpSmem = (257 + 64 + 64) * 68 * (int)sizeof(float);

    // layer 0 aggregation
    k_zero4<<<4096, 256>>>((float4*)p_agg, aggN4);
    k_zero4<<<64, 256>>>((float4*)p_deg, NN / 4);
    k_scatter<<<scatterBlocks, 256>>>(x, src, dst, (float*)p_agg, (float*)p_deg, 1);
    k_invdeg<<<(NN + 255) / 256, 256>>>();
    // layer 0 GEMM + BN + lrelu
    k_sage<<<sageBlocks, 256>>>(x, ws0, wn0, b0, g0, be0, rm0, rv0, (float*)p_h0);
    // layer 1 aggregation
    k_zero4<<<4096, 256>>>((float4*)p_agg, aggN4);
    k_scatter<<<scatterBlocks, 256>>>((const float*)p_h0, src, dst, (float*)p_agg,
                                      (float*)p_deg, 0);
    // layer 1 GEMM + BN + lrelu
    k_sage<<<sageBlocks, 256>>>((const float*)p_h0, ws1, wn1, b1, g1, be1, rm1, rv1,
                                (float*)p_h1);
    // candidate MLP
    k_mlp<<<mlpBlocks, 128, mlpSmem>>>(cu, cv, cf, mw0, mb0, mw1, mb1, mw2, mb2);
    // softmax + output
    k_max_part<<<256, 256>>>();
    k_sumexp<<<1, 1024>>>();
    k_writeout<<<(CC + 255) / 256, 256>>>(out, out_size);
}

// round 3
// speedup vs baseline: 1.6773x; 1.6773x over previous
#include <cuda_runtime.h>
#include <math.h>

#define NN 50000
#define EE 800000
#define CC 100000
#define DD 128
#define SCAN_B 196   // ceil(NN/256)

// ---------------- scratch (static device globals; no allocation) -------------
__device__ float g_agg[NN * DD];
__device__ float g_h0[NN * DD];
__device__ float g_h1[NN * DD];
__device__ float g_y[CC];
__device__ float g_pmax[256];
__device__ float g_MS[2];
// CSR build
__device__ int   g_cnt[SCAN_B * 256];
__device__ int   g_off[NN + 1];
__device__ int   g_cur[NN];
__device__ float g_inv[NN];
__device__ int   g_part[256];
__device__ int   g_ssrc[EE];

// ---------------- CSR build ---------------------------------------------------
__global__ void k_zero_cnt() {
    int i = blockIdx.x * blockDim.x + threadIdx.x;
    if (i < SCAN_B * 256) g_cnt[i] = 0;
}

__global__ void k_hist(const int* __restrict__ dst) {
    int e = blockIdx.x * blockDim.x + threadIdx.x;
    if (e < EE) atomicAdd(&g_cnt[__ldg(dst + e)], 1);
}

__global__ __launch_bounds__(256) void k_blocksum() {
    __shared__ int s[256];
    int t = threadIdx.x;
    int idx = blockIdx.x * 256 + t;
    s[t] = (idx < NN) ? g_cnt[idx] : 0;
    __syncthreads();
    for (int o = 128; o > 0; o >>= 1) {
        if (t < o) s[t] += s[t + o];
        __syncthreads();
    }
    if (t == 0) g_part[blockIdx.x] = s[0];
}

__global__ __launch_bounds__(256) void k_scanpart() {
    __shared__ int s[256];
    int t = threadIdx.x;
    int v = (t < SCAN_B) ? g_part[t] : 0;
    s[t] = v;
    __syncthreads();
    // Kogge-Stone inclusive
    for (int o = 1; o < 256; o <<= 1) {
        int add = (t >= o) ? s[t - o] : 0;
        __syncthreads();
        s[t] += add;
        __syncthreads();
    }
    g_part[t] = s[t] - v;   // exclusive
}

__global__ __launch_bounds__(256) void k_offsets() {
    __shared__ int s[256];
    int t = threadIdx.x;
    int idx = blockIdx.x * 256 + t;
    int cnt = (idx < NN) ? g_cnt[idx] : 0;
    s[t] = cnt;
    __syncthreads();
    for (int o = 1; o < 256; o <<= 1) {
        int add = (t >= o) ? s[t - o] : 0;
        __syncthreads();
        s[t] += add;
        __syncthreads();
    }
    int off = g_part[blockIdx.x] + s[t] - cnt;  // exclusive global offset
    if (idx < NN) {
        g_off[idx] = off;
        g_cur[idx] = off;
        g_inv[idx] = 1.0f / fmaxf((float)cnt, 1.0f);
        if (idx == NN - 1) g_off[NN] = off + cnt;
    }
}

__global__ void k_fill(const int* __restrict__ src, const int* __restrict__ dst) {
    int e = blockIdx.x * blockDim.x + threadIdx.x;
    if (e >= EE) return;
    int d = __ldg(dst + e);
    int pos = atomicAdd(&g_cur[d], 1);
    g_ssrc[pos] = __ldg(src + e);
}

// ---------------- gather aggregation: one warp per node -----------------------
// agg[n] = (1/max(deg,1)) * sum_{e in CSR(n)} feat[ssrc[e]]
__global__ __launch_bounds__(256) void k_agg(const float* __restrict__ feat,
                                             float* __restrict__ agg) {
    int w = (blockIdx.x * 256 + threadIdx.x) >> 5;
    int lane = threadIdx.x & 31;
    if (w >= NN) return;
    int beg = g_off[w], end = g_off[w + 1];
    float4 a0 = make_float4(0.f, 0.f, 0.f, 0.f);
    float4 a1 = make_float4(0.f, 0.f, 0.f, 0.f);
    float4 a2 = make_float4(0.f, 0.f, 0.f, 0.f);
    float4 a3 = make_float4(0.f, 0.f, 0.f, 0.f);
    int e = beg;
    for (; e + 3 < end; e += 4) {
        int s0 = __ldg(g_ssrc + e);
        int s1 = __ldg(g_ssrc + e + 1);
        int s2 = __ldg(g_ssrc + e + 2);
        int s3 = __ldg(g_ssrc + e + 3);
        float4 v0 = *reinterpret_cast<const float4*>(feat + (size_t)s0 * DD + lane * 4);
        float4 v1 = *reinterpret_cast<const float4*>(feat + (size_t)s1 * DD + lane * 4);
        float4 v2 = *reinterpret_cast<const float4*>(feat + (size_t)s2 * DD + lane * 4);
        float4 v3 = *reinterpret_cast<const float4*>(feat + (size_t)s3 * DD + lane * 4);
        a0.x += v0.x; a0.y += v0.y; a0.z += v0.z; a0.w += v0.w;
        a1.x += v1.x; a1.y += v1.y; a1.z += v1.z; a1.w += v1.w;
        a2.x += v2.x; a2.y += v2.y; a2.z += v2.z; a2.w += v2.w;
        a3.x += v3.x; a3.y += v3.y; a3.z += v3.z; a3.w += v3.w;
    }
    for (; e < end; e++) {
        int s0 = __ldg(g_ssrc + e);
        float4 v0 = *reinterpret_cast<const float4*>(feat + (size_t)s0 * DD + lane * 4);
        a0.x += v0.x; a0.y += v0.y; a0.z += v0.z; a0.w += v0.w;
    }
    float inv = g_inv[w];
    float4 r;
    r.x = (a0.x + a1.x + a2.x + a3.x) * inv;
    r.y = (a0.y + a1.y + a2.y + a3.y) * inv;
    r.z = (a0.z + a1.z + a2.z + a3.z) * inv;
    r.w = (a0.w + a1.w + a2.w + a3.w) * inv;
    *reinterpret_cast<float4*>(agg + (size_t)w * DD + lane * 4) = r;
}

// ---------------- fused SAGE layer: [64 nodes x 128 out], K=256 --------------
// h = lrelu( s * (X@Ws + AGG@Wn + b - rm) + beta ),  s = gamma*rsqrt(rv+eps)
// (AGG is already mean-normalized by k_agg)
__global__ __launch_bounds__(256) void k_sage(
    const float* __restrict__ X, const float* __restrict__ Wself,
    const float* __restrict__ Wneigh, const float* __restrict__ bias,
    const float* __restrict__ gamma, const float* __restrict__ beta,
    const float* __restrict__ rm, const float* __restrict__ rv,
    float* __restrict__ OUT) {
    __shared__ float As[16 * 68];    // [kk][node], padded
    __shared__ float Ws[16 * 128];   // [kk][j]

    int t = threadIdx.x;
    int tj = t & 31;          // j tile: j = tj*4 + jj
    int tn = t >> 5;          // node tile: n = tn*8 + i
    int base = blockIdx.x * 64;

    float4 acc[8];
#pragma unroll
    for (int i = 0; i < 8; i++) acc[i] = make_float4(0.f, 0.f, 0.f, 0.f);

    int kkA = t & 15, n0 = t >> 4;       // A-tile load mapping
    int jW = t & 127, kk0 = t >> 7;      // W-tile load mapping

    for (int kb = 0; kb < 256; kb += 16) {
        const bool selfPart = (kb < 128);
        const int koff = selfPart ? kb : kb - 128;
        const float* SRC = selfPart ? X : g_agg;
        const float* WSRC = selfPart ? Wself : Wneigh;
#pragma unroll
        for (int i = 0; i < 4; i++) {
            int n = n0 + 16 * i;
            int row = base + n;
            float v = 0.f;
            if (row < NN) v = __ldg(SRC + (size_t)row * DD + koff + kkA);
            As[kkA * 68 + n] = v;
        }
#pragma unroll
        for (int i = 0; i < 8; i++) {
            int kk = kk0 + 2 * i;
            Ws[kk * 128 + jW] = __ldg(WSRC + (size_t)(koff + kk) * DD + jW);
        }
        __syncthreads();
#pragma unroll
        for (int kk = 0; kk < 16; kk++) {
            float4 w = *reinterpret_cast<float4*>(Ws + kk * 128 + tj * 4);
            float4 a0 = *reinterpret_cast<float4*>(As + kk * 68 + tn * 8);
            float4 a1 = *reinterpret_cast<float4*>(As + kk * 68 + tn * 8 + 4);
            float av[8] = {a0.x, a0.y, a0.z, a0.w, a1.x, a1.y, a1.z, a1.w};
#pragma unroll
            for (int i = 0; i < 8; i++) {
                acc[i].x += av[i] * w.x;
                acc[i].y += av[i] * w.y;
                acc[i].z += av[i] * w.z;
                acc[i].w += av[i] * w.w;
            }
        }
        __syncthreads();
    }

    // folded BatchNorm + bias + leaky relu epilogue
    int j = tj * 4;
    float4 g = *reinterpret_cast<const float4*>(gamma + j);
    float4 rvv = *reinterpret_cast<const float4*>(rv + j);
    float4 bb = *reinterpret_cast<const float4*>(bias + j);
    float4 rmm = *reinterpret_cast<const float4*>(rm + j);
    float4 be = *reinterpret_cast<const float4*>(beta + j);
    float4 s, sh;
    s.x = g.x * rsqrtf(rvv.x + 1e-5f);
    s.y = g.y * rsqrtf(rvv.y + 1e-5f);
    s.z = g.z * rsqrtf(rvv.z + 1e-5f);
    s.w = g.w * rsqrtf(rvv.w + 1e-5f);
    sh.x = s.x * (bb.x - rmm.x) + be.x;
    sh.y = s.y * (bb.y - rmm.y) + be.y;
    sh.z = s.z * (bb.z - rmm.z) + be.z;
    sh.w = s.w * (bb.w - rmm.w) + be.w;
#pragma unroll
    for (int i = 0; i < 8; i++) {
        int row = base + tn * 8 + i;
        if (row >= NN) continue;
        float4 v;
        v.x = s.x * acc[i].x + sh.x;
        v.y = s.y * acc[i].y + sh.y;
        v.z = s.z * acc[i].z + sh.z;
        v.w = s.w * acc[i].w + sh.w;
        v.x = v.x > 0.f ? v.x : 0.01f * v.x;
        v.y = v.y > 0.f ? v.y : 0.01f * v.y;
        v.z = v.z > 0.f ? v.z : 0.01f * v.z;
        v.w = v.w > 0.f ? v.w : 0.01f * v.w;
        *reinterpret_cast<float4*>(OUT + (size_t)row * DD + tj * 4) = v;
    }
}

// ---------------- candidate MLP: [64 cands] per block, 3 layers --------------
__global__ __launch_bounds__(128) void k_mlp(
    const int* __restrict__ cu, const int* __restrict__ cv,
    const float* __restrict__ cf,
    const float* __restrict__ mw0, const float* __restrict__ mb0,
    const float* __restrict__ mw1, const float* __restrict__ mb1,
    const float* __restrict__ mw2, const float* __restrict__ mb2) {
    extern __shared__ float sm[];
    float* Ce = sm;               // [257][68]  (k, cand)
    float* Z1 = sm + 257 * 68;    // [64][68]
    float* Z2 = Z1 + 64 * 68;     // [64][68]

    int t = threadIdx.x;
    int cbase = blockIdx.x * 64;
    int w = t >> 5, lane = t & 31;

    // build candidate embedding tile (transposed): Ce[k][c]
    for (int ci = 0; ci < 16; ci++) {
        int c = w * 16 + ci;
        int cg = cbase + c;
        int cgc = cg < CC ? cg : 0;
        int u = __ldg(cu + cgc);
        int v = __ldg(cv + cgc);
#pragma unroll
        for (int kk = 0; kk < 4; kk++) {
            int k = lane + kk * 32;
            Ce[k * 68 + c] = g_h1[(size_t)u * DD + k];
            Ce[(k + 128) * 68 + c] = g_h1[(size_t)v * DD + k];
        }
        if (lane == 0) Ce[256 * 68 + c] = __ldg(cf + cgc);
    }
    __syncthreads();

    int tj = t & 15;   // j = tj*4 + jj
    int tc = t >> 4;   // c = tc*8 + i
    float4 acc[8];
#pragma unroll
    for (int i = 0; i < 8; i++) acc[i] = make_float4(0.f, 0.f, 0.f, 0.f);

    // layer 0: K = 257
    for (int k = 0; k < 257; k++) {
        float4 wv = __ldg(reinterpret_cast<const float4*>(mw0 + k * 64 + tj * 4));
        float4 a0 = *reinterpret_cast<float4*>(Ce + k * 68 + tc * 8);
        float4 a1 = *reinterpret_cast<float4*>(Ce + k * 68 + tc * 8 + 4);
        float av[8] = {a0.x, a0.y, a0.z, a0.w, a1.x, a1.y, a1.z, a1.w};
#pragma unroll
        for (int i = 0; i < 8; i++) {
            acc[i].x += av[i] * wv.x;
            acc[i].y += av[i] * wv.y;
            acc[i].z += av[i] * wv.z;
            acc[i].w += av[i] * wv.w;
        }
    }
    {
        float4 bv = __ldg(reinterpret_cast<const float4*>(mb0 + tj * 4));
#pragma unroll
        for (int i = 0; i < 8; i++) {
            float vx = acc[i].x + bv.x; vx = vx > 0.f ? vx : 0.01f * vx;
            float vy = acc[i].y + bv.y; vy = vy > 0.f ? vy : 0.01f * vy;
            float vz = acc[i].z + bv.z; vz = vz > 0.f ? vz : 0.01f * vz;
            float vw = acc[i].w + bv.w; vw = vw > 0.f ? vw : 0.01f * vw;
            int c = tc * 8 + i;
            Z1[(tj * 4 + 0) * 68 + c] = vx;
            Z1[(tj * 4 + 1) * 68 + c] = vy;
            Z1[(tj * 4 + 2) * 68 + c] = vz;
            Z1[(tj * 4 + 3) * 68 + c] = vw;
        }
    }
    __syncthreads();

    // layer 1: K = 64
#pragma unroll
    for (int i = 0; i < 8; i++) acc[i] = make_float4(0.f, 0.f, 0.f, 0.f);
    for (int k = 0; k < 64; k++) {
        float4 wv = __ldg(reinterpret_cast<const float4*>(mw1 + k * 64 + tj * 4));
        float4 a0 = *reinterpret_cast<float4*>(Z1 + k * 68 + tc * 8);
        float4 a1 = *reinterpret_cast<float4*>(Z1 + k * 68 + tc * 8 + 4);
        float av[8] = {a0.x, a0.y, a0.z, a0.w, a1.x, a1.y, a1.z, a1.w};
#pragma unroll
        for (int i = 0; i < 8; i++) {
            acc[i].x += av[i] * wv.x;
            acc[i].y += av[i] * wv.y;
            acc[i].z += av[i] * wv.z;
            acc[i].w += av[i] * wv.w;
        }
    }
    {
        float4 bv = __ldg(reinterpret_cast<const float4*>(mb1 + tj * 4));
#pragma unroll
        for (int i = 0; i < 8; i++) {
            float vx = acc[i].x + bv.x; vx = vx > 0.f ? vx : 0.01f * vx;
            float vy = acc[i].y + bv.y; vy = vy > 0.f ? vy : 0.01f * vy;
            float vz = acc[i].z + bv.z; vz = vz > 0.f ? vz : 0.01f * vz;
            float vw = acc[i].w + bv.w; vw = vw > 0.f ? vw : 0.01f * vw;
            int c = tc * 8 + i;
            Z2[(tj * 4 + 0) * 68 + c] = vx;
            Z2[(tj * 4 + 1) * 68 + c] = vy;
            Z2[(tj * 4 + 2) * 68 + c] = vz;
            Z2[(tj * 4 + 3) * 68 + c] = vw;
        }
    }
    __syncthreads();

    // layer 2: y[c] = z2 . mw2 + mb2
    if (t < 64) {
        int c = t;
        float a = __ldg(mb2);
#pragma unroll 8
        for (int j = 0; j < 64; j++) a += Z2[j * 68 + c] * __ldg(mw2 + j);
        int cg = cbase + c;
        if (cg < CC) g_y[cg] = a;
    }
}

// ---------------- softmax over C ---------------------------------------------
__global__ void k_max_part() {
    __shared__ float s[256];
    int t = threadIdx.x;
    float m = -1e30f;
    for (int i = blockIdx.x * 256 + t; i < CC; i += 256 * 256) m = fmaxf(m, g_y[i]);
    s[t] = m;
    __syncthreads();
    for (int o = 128; o > 0; o >>= 1) {
        if (t < o) s[t] = fmaxf(s[t], s[t + o]);
        __syncthreads();
    }
    if (t == 0) g_pmax[blockIdx.x] = s[0];
}

__global__ void k_sumexp() {
    __shared__ float s[1024];
    int t = threadIdx.x;
    s[t] = (t < 256) ? g_pmax[t] : -1e30f;
    __syncthreads();
    for (int o = 512; o > 0; o >>= 1) {
        if (t < o) s[t] = fmaxf(s[t], s[t + o]);
        __syncthreads();
    }
    float M = s[0];
    __syncthreads();
    float sum = 0.f;
    for (int i = t; i < CC; i += 1024) sum += expf(g_y[i] - M);
    s[t] = sum;
    __syncthreads();
    for (int o = 512; o > 0; o >>= 1) {
        if (t < o) s[t] += s[t + o];
        __syncthreads();
    }
    if (t == 0) { g_MS[0] = M; g_MS[1] = s[0]; }
}

__global__ void k_writeout(float* __restrict__ out, int out_size) {
    int i = blockIdx.x * blockDim.x + threadIdx.x;
    if (i >= CC) return;
    float y = g_y[i];
    if (out_size >= CC) out[i] = y;
    if (out_size >= 2 * CC) out[CC + i] = expf(y - g_MS[0]) / g_MS[1];
}

// ---------------- launch -----------------------------------------------------
extern "C" void kernel_launch(void* const* d_in, const int* in_sizes, int n_in,
                              void* d_out, int out_size) {
    const float* x   = (const float*)d_in[0];
    const int*   src = (const int*)d_in[1];
    const int*   dst = (const int*)d_in[2];
    const int*   cu  = (const int*)d_in[3];
    const int*   cv  = (const int*)d_in[4];
    const float* cf  = (const float*)d_in[5];
    const float* ws0 = (const float*)d_in[6];
    const float* wn0 = (const float*)d_in[7];
    const float* b0  = (const float*)d_in[8];
    const float* g0  = (const float*)d_in[9];
    const float* be0 = (const float*)d_in[10];
    const float* rm0 = (const float*)d_in[11];
    const float* rv0 = (const float*)d_in[12];
    const float* ws1 = (const float*)d_in[13];
    const float* wn1 = (const float*)d_in[14];
    const float* b1  = (const float*)d_in[15];
    const float* g1  = (const float*)d_in[16];
    const float* be1 = (const float*)d_in[17];
    const float* rm1 = (const float*)d_in[18];
    const float* rv1 = (const float*)d_in[19];
    const float* mw0 = (const float*)d_in[20];
    const float* mb0 = (const float*)d_in[21];
    const float* mw1 = (const float*)d_in[22];
    const float* mb1 = (const float*)d_in[23];
    const float* mw2 = (const float*)d_in[24];
    const float* mb2 = (const float*)d_in[25];
    float* out = (float*)d_out;

    void *p_agg = nullptr, *p_h0 = nullptr, *p_h1 = nullptr;
    cudaGetSymbolAddress(&p_agg, g_agg);
    cudaGetSymbolAddress(&p_h0, g_h0);
    cudaGetSymbolAddress(&p_h1, g_h1);

    static bool attr_set = false;
    if (!attr_set) {
        cudaFuncSetAttribute(k_mlp, cudaFuncAttributeMaxDynamicSharedMemorySize,
                             (257 + 64 + 64) * 68 * (int)sizeof(float));
        attr_set = true;
    }

    const int sageBlocks = (NN + 63) / 64;
    const int mlpBlocks = (CC + 63) / 64;
    const int mlpSmem = (257 + 64 + 64) * 68 * (int)sizeof(float);
    const int aggBlocks = (NN * 32 + 255) / 256;

    // ---- CSR build (once per call; shared by both layers) ----
    k_zero_cnt<<<SCAN_B, 256>>>();
    k_hist<<<(EE + 255) / 256, 256>>>(dst);
    k_blocksum<<<SCAN_B, 256>>>();
    k_scanpart<<<1, 256>>>();
    k_offsets<<<SCAN_B, 256>>>();
    k_fill<<<(EE + 255) / 256, 256>>>(src, dst);

    // ---- layer 0 ----
    k_agg<<<aggBlocks, 256>>>(x, (float*)p_agg);
    k_sage<<<sageBlocks, 256>>>(x, ws0, wn0, b0, g0, be0, rm0, rv0, (float*)p_h0);
    // ---- layer 1 ----
    k_agg<<<aggBlocks, 256>>>((const float*)p_h0, (float*)p_agg);
    k_sage<<<sageBlocks, 256>>>((const float*)p_h0, ws1, wn1, b1, g1, be1, rm1, rv1,
                                (float*)p_h1);
    // ---- candidate MLP ----
    k_mlp<<<mlpBlocks, 128, mlpSmem>>>(cu, cv, cf, mw0, mb0, mw1, mb1, mw2, mb2);
    // ---- softmax + output ----
    k_max_part<<<256, 256>>>();
    k_sumexp<<<1, 1024>>>();
    k_writeout<<<(CC + 255) / 256, 256>>>(out, out_size);
}

// round 4
// speedup vs baseline: 1.8410x; 1.0976x over previous
#include <cuda_runtime.h>
#include <math.h>

#define NN 50000
#define EE 800000
#define CC 100000
#define DD 128
#define SCAN_B 196   // ceil(NN/256)

typedef unsigned long long ull;

// ---------------- f32x2 packed-math helpers ----------------------------------
__device__ __forceinline__ ull pack2(float a, float b) {
    ull r;
    asm("mov.b64 %0, {%1, %2};" : "=l"(r) : "f"(a), "f"(b));
    return r;
}
__device__ __forceinline__ void ffma2(ull& d, ull a, ull b) {
    asm("fma.rn.f32x2 %0, %1, %2, %0;" : "+l"(d) : "l"(a), "l"(b));
}
__device__ __forceinline__ float2 unpack2(ull v) {
    float2 r;
    asm("mov.b64 {%0, %1}, %2;" : "=f"(r.x), "=f"(r.y) : "l"(v));
    return r;
}

// ---------------- scratch (static device globals; no allocation) -------------
__device__ float g_agg[NN * DD];
__device__ float g_h0[NN * DD];
__device__ float g_h1[NN * DD];
__device__ float g_y[CC];
__device__ float g_pmax[256];
__device__ float g_MS[2];
// CSR build
__device__ int   g_cnt[SCAN_B * 256];
__device__ int   g_off[NN + 1];
__device__ int   g_cur[NN];
__device__ float g_inv[NN];
__device__ int   g_part[256];
__device__ int   g_ssrc[EE];

// ---------------- CSR build ---------------------------------------------------
__global__ void k_zero_cnt() {
    int i = blockIdx.x * blockDim.x + threadIdx.x;
    if (i < SCAN_B * 256) g_cnt[i] = 0;
}

__global__ void k_hist(const int* __restrict__ dst) {
    int e = blockIdx.x * blockDim.x + threadIdx.x;
    if (e < EE) atomicAdd(&g_cnt[__ldg(dst + e)], 1);
}

__global__ __launch_bounds__(256) void k_blocksum() {
    __shared__ int s[256];
    int t = threadIdx.x;
    int idx = blockIdx.x * 256 + t;
    s[t] = (idx < NN) ? g_cnt[idx] : 0;
    __syncthreads();
    for (int o = 128; o > 0; o >>= 1) {
        if (t < o) s[t] += s[t + o];
        __syncthreads();
    }
    if (t == 0) g_part[blockIdx.x] = s[0];
}

__global__ __launch_bounds__(256) void k_scanpart() {
    __shared__ int s[256];
    int t = threadIdx.x;
    int v = (t < SCAN_B) ? g_part[t] : 0;
    s[t] = v;
    __syncthreads();
    for (int o = 1; o < 256; o <<= 1) {
        int add = (t >= o) ? s[t - o] : 0;
        __syncthreads();
        s[t] += add;
        __syncthreads();
    }
    g_part[t] = s[t] - v;   // exclusive
}

__global__ __launch_bounds__(256) void k_offsets() {
    __shared__ int s[256];
    int t = threadIdx.x;
    int idx = blockIdx.x * 256 + t;
    int cnt = (idx < NN) ? g_cnt[idx] : 0;
    s[t] = cnt;
    __syncthreads();
    for (int o = 1; o < 256; o <<= 1) {
        int add = (t >= o) ? s[t - o] : 0;
        __syncthreads();
        s[t] += add;
        __syncthreads();
    }
    int off = g_part[blockIdx.x] + s[t] - cnt;  // exclusive global offset
    if (idx < NN) {
        g_off[idx] = off;
        g_cur[idx] = off;
        g_inv[idx] = 1.0f / fmaxf((float)cnt, 1.0f);
        if (idx == NN - 1) g_off[NN] = off + cnt;
    }
}

__global__ void k_fill(const int* __restrict__ src, const int* __restrict__ dst) {
    int e = blockIdx.x * blockDim.x + threadIdx.x;
    if (e >= EE) return;
    int d = __ldg(dst + e);
    int pos = atomicAdd(&g_cur[d], 1);
    g_ssrc[pos] = __ldg(src + e);
}

// ---------------- gather aggregation: one warp per node -----------------------
__global__ __launch_bounds__(256) void k_agg(const float* __restrict__ feat,
                                             float* __restrict__ agg) {
    int w = (blockIdx.x * 256 + threadIdx.x) >> 5;
    int lane = threadIdx.x & 31;
    if (w >= NN) return;
    int beg = g_off[w], end = g_off[w + 1];
    float4 a0 = make_float4(0.f, 0.f, 0.f, 0.f);
    float4 a1 = make_float4(0.f, 0.f, 0.f, 0.f);
    float4 a2 = make_float4(0.f, 0.f, 0.f, 0.f);
    float4 a3 = make_float4(0.f, 0.f, 0.f, 0.f);
    int e = beg;
    for (; e + 3 < end; e += 4) {
        int s0 = __ldg(g_ssrc + e);
        int s1 = __ldg(g_ssrc + e + 1);
        int s2 = __ldg(g_ssrc + e + 2);
        int s3 = __ldg(g_ssrc + e + 3);
        float4 v0 = *reinterpret_cast<const float4*>(feat + (size_t)s0 * DD + lane * 4);
        float4 v1 = *reinterpret_cast<const float4*>(feat + (size_t)s1 * DD + lane * 4);
        float4 v2 = *reinterpret_cast<const float4*>(feat + (size_t)s2 * DD + lane * 4);
        float4 v3 = *reinterpret_cast<const float4*>(feat + (size_t)s3 * DD + lane * 4);
        a0.x += v0.x; a0.y += v0.y; a0.z += v0.z; a0.w += v0.w;
        a1.x += v1.x; a1.y += v1.y; a1.z += v1.z; a1.w += v1.w;
        a2.x += v2.x; a2.y += v2.y; a2.z += v2.z; a2.w += v2.w;
        a3.x += v3.x; a3.y += v3.y; a3.z += v3.z; a3.w += v3.w;
    }
    for (; e < end; e++) {
        int s0 = __ldg(g_ssrc + e);
        float4 v0 = *reinterpret_cast<const float4*>(feat + (size_t)s0 * DD + lane * 4);
        a0.x += v0.x; a0.y += v0.y; a0.z += v0.z; a0.w += v0.w;
    }
    float inv = g_inv[w];
    float4 r;
    r.x = (a0.x + a1.x + a2.x + a3.x) * inv;
    r.y = (a0.y + a1.y + a2.y + a3.y) * inv;
    r.z = (a0.z + a1.z + a2.z + a3.z) * inv;
    r.w = (a0.w + a1.w + a2.w + a3.w) * inv;
    *reinterpret_cast<float4*>(agg + (size_t)w * DD + lane * 4) = r;
}

// ---------------- fused SAGE layer: [128 nodes x 128 out], K=256, f32x2 ------
// h = lrelu( s * (X@Ws + AGG@Wn + b - rm) + beta ),  s = gamma*rsqrt(rv+eps)
#define SB_PAD 132
__global__ __launch_bounds__(256, 2) void k_sage(
    const float* __restrict__ X, const float* __restrict__ Wself,
    const float* __restrict__ Wneigh, const float* __restrict__ bias,
    const float* __restrict__ gamma, const float* __restrict__ beta,
    const float* __restrict__ rm, const float* __restrict__ rv,
    float* __restrict__ OUT) {
    __shared__ __align__(16) float As[16 * SB_PAD];   // [kk][node]
    __shared__ __align__(16) float Ws[16 * 128];      // [kk][j]

    int t = threadIdx.x;
    int tj = t & 15;          // j group: j = tj*8
    int tn = t >> 4;          // node group: node = base + tn*8 + i
    int base = blockIdx.x * 128;

    ull acc[8][4];
#pragma unroll
    for (int i = 0; i < 8; i++)
#pragma unroll
        for (int p = 0; p < 4; p++) acc[i][p] = 0ULL;

    int kkA = t & 15, n0 = t >> 4;       // A-tile load: node n0+16i, k kkA
    int jW = t & 127, kk0 = t >> 7;      // W-tile load

    for (int kb = 0; kb < 256; kb += 16) {
        const bool selfPart = (kb < 128);
        const int koff = selfPart ? kb : kb - 128;
        const float* SRC = selfPart ? X : g_agg;
        const float* WSRC = selfPart ? Wself : Wneigh;
#pragma unroll
        for (int i = 0; i < 8; i++) {
            int n = n0 + 16 * i;
            int row = base + n;
            float v = 0.f;
            if (row < NN) v = __ldg(SRC + (size_t)row * DD + koff + kkA);
            As[kkA * SB_PAD + n] = v;
        }
#pragma unroll
        for (int i = 0; i < 8; i++) {
            int kk = kk0 + 2 * i;
            Ws[kk * 128 + jW] = __ldg(WSRC + (size_t)(koff + kk) * DD + jW);
        }
        __syncthreads();
#pragma unroll
        for (int kk = 0; kk < 16; kk++) {
            const float* wrow = Ws + kk * 128 + tj * 8;
            ull w01 = *reinterpret_cast<const ull*>(wrow + 0);
            ull w23 = *reinterpret_cast<const ull*>(wrow + 2);
            ull w45 = *reinterpret_cast<const ull*>(wrow + 4);
            ull w67 = *reinterpret_cast<const ull*>(wrow + 6);
            float4 a0 = *reinterpret_cast<float4*>(As + kk * SB_PAD + tn * 8);
            float4 a1 = *reinterpret_cast<float4*>(As + kk * SB_PAD + tn * 8 + 4);
            float av[8] = {a0.x, a0.y, a0.z, a0.w, a1.x, a1.y, a1.z, a1.w};
#pragma unroll
            for (int i = 0; i < 8; i++) {
                ull ap = pack2(av[i], av[i]);
                ffma2(acc[i][0], ap, w01);
                ffma2(acc[i][1], ap, w23);
                ffma2(acc[i][2], ap, w45);
                ffma2(acc[i][3], ap, w67);
            }
        }
        __syncthreads();
    }

    // folded BatchNorm + bias + leaky relu epilogue (8 j per thread)
    int j = tj * 8;
    float sj[8], shj[8];
#pragma unroll
    for (int q = 0; q < 8; q++) {
        float gq = __ldg(gamma + j + q);
        float rq = __ldg(rv + j + q);
        float bq = __ldg(bias + j + q);
        float mq = __ldg(rm + j + q);
        float eq = __ldg(beta + j + q);
        sj[q] = gq * rsqrtf(rq + 1e-5f);
        shj[q] = sj[q] * (bq - mq) + eq;
    }
#pragma unroll
    for (int i = 0; i < 8; i++) {
        int row = base + tn * 8 + i;
        if (row >= NN) continue;
        float o[8];
#pragma unroll
        for (int p = 0; p < 4; p++) {
            float2 v = unpack2(acc[i][p]);
            o[2 * p] = v.x;
            o[2 * p + 1] = v.y;
        }
        float4 r0, r1;
        float* rr = &r0.x;
#pragma unroll
        for (int q = 0; q < 8; q++) {
            float v = sj[q] * o[q] + shj[q];
            v = v > 0.f ? v : 0.01f * v;
            if (q < 4) (&r0.x)[q] = v; else (&r1.x)[q - 4] = v;
        }
        (void)rr;
        *reinterpret_cast<float4*>(OUT + (size_t)row * DD + j) = r0;
        *reinterpret_cast<float4*>(OUT + (size_t)row * DD + j + 4) = r1;
    }
}

// ---------------- candidate MLP: [64 cands] per block, 3 layers, f32x2 -------
__global__ __launch_bounds__(128) void k_mlp(
    const int* __restrict__ cu, const int* __restrict__ cv,
    const float* __restrict__ cf,
    const float* __restrict__ mw0, const float* __restrict__ mb0,
    const float* __restrict__ mw1, const float* __restrict__ mb1,
    const float* __restrict__ mw2, const float* __restrict__ mb2) {
    extern __shared__ float sm[];
    float* Ce = sm;               // [257][68]  (k, cand)
    float* Z1 = sm + 257 * 68;    // [64][68]
    float* Z2 = Z1 + 64 * 68;     // [64][68]

    int t = threadIdx.x;
    int cbase = blockIdx.x * 64;
    int w = t >> 5, lane = t & 31;

    // build candidate embedding tile (transposed): Ce[k][c]
    for (int ci = 0; ci < 16; ci++) {
        int c = w * 16 + ci;
        int cg = cbase + c;
        int cgc = cg < CC ? cg : 0;
        int u = __ldg(cu + cgc);
        int v = __ldg(cv + cgc);
#pragma unroll
        for (int kk = 0; kk < 4; kk++) {
            int k = lane + kk * 32;
            Ce[k * 68 + c] = g_h1[(size_t)u * DD + k];
            Ce[(k + 128) * 68 + c] = g_h1[(size_t)v * DD + k];
        }
        if (lane == 0) Ce[256 * 68 + c] = __ldg(cf + cgc);
    }
    __syncthreads();

    int tj = t & 15;   // j = tj*4 + jj
    int tc = t >> 4;   // c = tc*8 + i
    ull acc[8][2];
#pragma unroll
    for (int i = 0; i < 8; i++) { acc[i][0] = 0ULL; acc[i][1] = 0ULL; }

    // layer 0: K = 257
    for (int k = 0; k < 257; k++) {
        float4 wv = __ldg(reinterpret_cast<const float4*>(mw0 + k * 64 + tj * 4));
        ull w01 = pack2(wv.x, wv.y);
        ull w23 = pack2(wv.z, wv.w);
        float4 a0 = *reinterpret_cast<float4*>(Ce + k * 68 + tc * 8);
        float4 a1 = *reinterpret_cast<float4*>(Ce + k * 68 + tc * 8 + 4);
        float av[8] = {a0.x, a0.y, a0.z, a0.w, a1.x, a1.y, a1.z, a1.w};
#pragma unroll
        for (int i = 0; i < 8; i++) {
            ull ap = pack2(av[i], av[i]);
            ffma2(acc[i][0], ap, w01);
            ffma2(acc[i][1], ap, w23);
        }
    }
    {
        float4 bv = __ldg(reinterpret_cast<const float4*>(mb0 + tj * 4));
#pragma unroll
        for (int i = 0; i < 8; i++) {
            float2 p0 = unpack2(acc[i][0]);
            float2 p1 = unpack2(acc[i][1]);
            float vx = p0.x + bv.x; vx = vx > 0.f ? vx : 0.01f * vx;
            float vy = p0.y + bv.y; vy = vy > 0.f ? vy : 0.01f * vy;
            float vz = p1.x + bv.z; vz = vz > 0.f ? vz : 0.01f * vz;
            float vw = p1.y + bv.w; vw = vw > 0.f ? vw : 0.01f * vw;
            int c = tc * 8 + i;
            Z1[(tj * 4 + 0) * 68 + c] = vx;
            Z1[(tj * 4 + 1) * 68 + c] = vy;
            Z1[(tj * 4 + 2) * 68 + c] = vz;
            Z1[(tj * 4 + 3) * 68 + c] = vw;
        }
    }
    __syncthreads();

    // layer 1: K = 64
#pragma unroll
    for (int i = 0; i < 8; i++) { acc[i][0] = 0ULL; acc[i][1] = 0ULL; }
    for (int k = 0; k < 64; k++) {
        float4 wv = __ldg(reinterpret_cast<const float4*>(mw1 + k * 64 + tj * 4));
        ull w01 = pack2(wv.x, wv.y);
        ull w23 = pack2(wv.z, wv.w);
        float4 a0 = *reinterpret_cast<float4*>(Z1 + k * 68 + tc * 8);
        float4 a1 = *reinterpret_cast<float4*>(Z1 + k * 68 + tc * 8 + 4);
        float av[8] = {a0.x, a0.y, a0.z, a0.w, a1.x, a1.y, a1.z, a1.w};
#pragma unroll
        for (int i = 0; i < 8; i++) {
            ull ap = pack2(av[i], av[i]);
            ffma2(acc[i][0], ap, w01);
            ffma2(acc[i][1], ap, w23);
        }
    }
    {
        float4 bv = __ldg(reinterpret_cast<const float4*>(mb1 + tj * 4));
#pragma unroll
        for (int i = 0; i < 8; i++) {
            float2 p0 = unpack2(acc[i][0]);
            float2 p1 = unpack2(acc[i][1]);
            float vx = p0.x + bv.x; vx = vx > 0.f ? vx : 0.01f * vx;
            float vy = p0.y + bv.y; vy = vy > 0.f ? vy : 0.01f * vy;
            float vz = p1.x + bv.z; vz = vz > 0.f ? vz : 0.01f * vz;
            float vw = p1.y + bv.w; vw = vw > 0.f ? vw : 0.01f * vw;
            int c = tc * 8 + i;
            Z2[(tj * 4 + 0) * 68 + c] = vx;
            Z2[(tj * 4 + 1) * 68 + c] = vy;
            Z2[(tj * 4 + 2) * 68 + c] = vz;
            Z2[(tj * 4 + 3) * 68 + c] = vw;
        }
    }
    __syncthreads();

    // layer 2: y[c] = z2 . mw2 + mb2
    if (t < 64) {
        int c = t;
        float a = __ldg(mb2);
#pragma unroll 8
        for (int j = 0; j < 64; j++) a += Z2[j * 68 + c] * __ldg(mw2 + j);
        int cg = cbase + c;
        if (cg < CC) g_y[cg] = a;
    }
}

// ---------------- softmax over C ---------------------------------------------
__global__ void k_max_part() {
    __shared__ float s[256];
    int t = threadIdx.x;
    float m = -1e30f;
    for (int i = blockIdx.x * 256 + t; i < CC; i += 256 * 256) m = fmaxf(m, g_y[i]);
    s[t] = m;
    __syncthreads();
    for (int o = 128; o > 0; o >>= 1) {
        if (t < o) s[t] = fmaxf(s[t], s[t + o]);
        __syncthreads();
    }
    if (t == 0) g_pmax[blockIdx.x] = s[0];
}

__global__ void k_sumexp() {
    __shared__ float s[1024];
    int t = threadIdx.x;
    s[t] = (t < 256) ? g_pmax[t] : -1e30f;
    __syncthreads();
    for (int o = 512; o > 0; o >>= 1) {
        if (t < o) s[t] = fmaxf(s[t], s[t + o]);
        __syncthreads();
    }
    float M = s[0];
    __syncthreads();
    float sum = 0.f;
    for (int i = t; i < CC; i += 1024) sum += expf(g_y[i] - M);
    s[t] = sum;
    __syncthreads();
    for (int o = 512; o > 0; o >>= 1) {
        if (t < o) s[t] += s[t + o];
        __syncthreads();
    }
    if (t == 0) { g_MS[0] = M; g_MS[1] = s[0]; }
}

__global__ void k_writeout(float* __restrict__ out, int out_size) {
    int i = blockIdx.x * blockDim.x + threadIdx.x;
    if (i >= CC) return;
    float y = g_y[i];
    if (out_size >= CC) out[i] = y;
    if (out_size >= 2 * CC) out[CC + i] = expf(y - g_MS[0]) / g_MS[1];
}

// ---------------- launch -----------------------------------------------------
extern "C" void kernel_launch(void* const* d_in, const int* in_sizes, int n_in,
                              void* d_out, int out_size) {
    const float* x   = (const float*)d_in[0];
    const int*   src = (const int*)d_in[1];
    const int*   dst = (const int*)d_in[2];
    const int*   cu  = (const int*)d_in[3];
    const int*   cv  = (const int*)d_in[4];
    const float* cf  = (const float*)d_in[5];
    const float* ws0 = (const float*)d_in[6];
    const float* wn0 = (const float*)d_in[7];
    const float* b0  = (const float*)d_in[8];
    const float* g0  = (const float*)d_in[9];
    const float* be0 = (const float*)d_in[10];
    const float* rm0 = (const float*)d_in[11];
    const float* rv0 = (const float*)d_in[12];
    const float* ws1 = (const float*)d_in[13];
    const float* wn1 = (const float*)d_in[14];
    const float* b1  = (const float*)d_in[15];
    const float* g1  = (const float*)d_in[16];
    const float* be1 = (const float*)d_in[17];
    const float* rm1 = (const float*)d_in[18];
    const float* rv1 = (const float*)d_in[19];
    const float* mw0 = (const float*)d_in[20];
    const float* mb0 = (const float*)d_in[21];
    const float* mw1 = (const float*)d_in[22];
    const float* mb1 = (const float*)d_in[23];
    const float* mw2 = (const float*)d_in[24];
    const float* mb2 = (const float*)d_in[25];
    float* out = (float*)d_out;

    void *p_agg = nullptr, *p_h0 = nullptr, *p_h1 = nullptr;
    cudaGetSymbolAddress(&p_agg, g_agg);
    cudaGetSymbolAddress(&p_h0, g_h0);
    cudaGetSymbolAddress(&p_h1, g_h1);

    static bool attr_set = false;
    if (!attr_set) {
        cudaFuncSetAttribute(k_mlp, cudaFuncAttributeMaxDynamicSharedMemorySize,
                             (257 + 64 + 64) * 68 * (int)sizeof(float));
        attr_set = true;
    }

    const int sageBlocks = (NN + 127) / 128;
    const int mlpBlocks = (CC + 63) / 64;
    const int mlpSmem = (257 + 64 + 64) * 68 * (int)sizeof(float);
    const int aggBlocks = (NN * 32 + 255) / 256;

    // ---- CSR build (once per call; shared by both layers) ----
    k_zero_cnt<<<SCAN_B, 256>>>();
    k_hist<<<(EE + 255) / 256, 256>>>(dst);
    k_blocksum<<<SCAN_B, 256>>>();
    k_scanpart<<<1, 256>>>();
    k_offsets<<<SCAN_B, 256>>>();
    k_fill<<<(EE + 255) / 256, 256>>>(src, dst);

    // ---- layer 0 ----
    k_agg<<<aggBlocks, 256>>>(x, (float*)p_agg);
    k_sage<<<sageBlocks, 256>>>(x, ws0, wn0, b0, g0, be0, rm0, rv0, (float*)p_h0);
    // ---- layer 1 ----
    k_agg<<<aggBlocks, 256>>>((const float*)p_h0, (float*)p_agg);
    k_sage<<<sageBlocks, 256>>>((const float*)p_h0, ws1, wn1, b1, g1, be1, rm1, rv1,
                                (float*)p_h1);
    // ---- candidate MLP ----
    k_mlp<<<mlpBlocks, 128, mlpSmem>>>(cu, cv, cf, mw0, mb0, mw1, mb1, mw2, mb2);
    // ---- softmax + output ----
    k_max_part<<<256, 256>>>();
    k_sumexp<<<1, 1024>>>();
    k_writeout<<<(CC + 255) / 256, 256>>>(out, out_size);
}

// round 5
// speedup vs baseline: 2.4477x; 1.3295x over previous
#include <cuda_runtime.h>
#include <math.h>

#define NN 50000
#define EE 800000
#define CC 100000
#define DD 128

typedef unsigned long long ull;

// ---------------- f32x2 packed-math helpers ----------------------------------
__device__ __forceinline__ ull pack2(float a, float b) {
    ull r;
    asm("mov.b64 %0, {%1, %2};" : "=l"(r) : "f"(a), "f"(b));
    return r;
}
__device__ __forceinline__ void ffma2(ull& d, ull a, ull b) {
    asm("fma.rn.f32x2 %0, %1, %2, %0;" : "+l"(d) : "l"(a), "l"(b));
}
__device__ __forceinline__ float2 unpack2(ull v) {
    float2 r;
    asm("mov.b64 {%0, %1}, %2;" : "=f"(r.x), "=f"(r.y) : "l"(v));
    return r;
}

// ---------------- scratch (static device globals; no allocation) -------------
__device__ float g_agg[NN * DD];
__device__ float g_h0[NN * DD];
__device__ float g_h1[NN * DD];
__device__ float g_pq[NN * DD];     // [n][0:64]=P(+mb0), [n][64:128]=Q
__device__ float g_y[CC];
__device__ float g_pmax[256];
__device__ float g_MS[2];
// CSR build
__device__ int   g_cnt[NN];
__device__ int   g_off[NN + 1];
__device__ int   g_cur[NN];
__device__ float g_inv[NN];
__device__ int   g_ssrc[EE];

// ---------------- CSR build ---------------------------------------------------
__global__ void k_zero_cnt() {
    int i = blockIdx.x * blockDim.x + threadIdx.x;
    if (i < NN) g_cnt[i] = 0;
}

__global__ void k_hist(const int* __restrict__ dst) {
    int e = blockIdx.x * blockDim.x + threadIdx.x;
    if (e < EE) atomicAdd(&g_cnt[__ldg(dst + e)], 1);
}

// single-block exclusive scan over g_cnt -> g_off/g_cur/g_inv
__global__ __launch_bounds__(1024) void k_scan() {
    __shared__ int wsum[32];
    __shared__ int carry_s;
    int t = threadIdx.x, lane = t & 31, wid = t >> 5;
    if (t == 0) carry_s = 0;
    __syncthreads();
    for (int base = 0; base < NN; base += 1024) {
        int idx = base + t;
        int cnt = (idx < NN) ? g_cnt[idx] : 0;
        int v = cnt;
#pragma unroll
        for (int o = 1; o < 32; o <<= 1) {
            int n = __shfl_up_sync(0xFFFFFFFFu, v, o);
            if (lane >= o) v += n;
        }
        if (lane == 31) wsum[wid] = v;
        __syncthreads();
        if (wid == 0) {
            int s = wsum[lane];
#pragma unroll
            for (int o = 1; o < 32; o <<= 1) {
                int n = __shfl_up_sync(0xFFFFFFFFu, s, o);
                if (lane >= o) s += n;
            }
            wsum[lane] = s;
        }
        __syncthreads();
        int incl = v + (wid > 0 ? wsum[wid - 1] : 0);
        int carry = carry_s;
        int off = carry + incl - cnt;
        if (idx < NN) {
            g_off[idx] = off;
            g_cur[idx] = off;
            g_inv[idx] = 1.0f / fmaxf((float)cnt, 1.0f);
        }
        __syncthreads();
        if (t == 1023) {
            carry_s = carry + incl;
            if (base + 1024 >= NN) g_off[NN] = carry + incl;
        }
        __syncthreads();
    }
}

__global__ void k_fill(const int* __restrict__ src, const int* __restrict__ dst) {
    int e = blockIdx.x * blockDim.x + threadIdx.x;
    if (e >= EE) return;
    int d = __ldg(dst + e);
    int pos = atomicAdd(&g_cur[d], 1);
    g_ssrc[pos] = __ldg(src + e);
}

// ---------------- gather aggregation: one warp per node -----------------------
__global__ __launch_bounds__(256) void k_agg(const float* __restrict__ feat,
                                             float* __restrict__ agg) {
    int w = (blockIdx.x * 256 + threadIdx.x) >> 5;
    int lane = threadIdx.x & 31;
    if (w >= NN) return;
    int beg = g_off[w], end = g_off[w + 1];
    float4 a0 = make_float4(0.f, 0.f, 0.f, 0.f);
    float4 a1 = make_float4(0.f, 0.f, 0.f, 0.f);
    float4 a2 = make_float4(0.f, 0.f, 0.f, 0.f);
    float4 a3 = make_float4(0.f, 0.f, 0.f, 0.f);
    int e = beg;
    for (; e + 3 < end; e += 4) {
        int s0 = __ldg(g_ssrc + e);
        int s1 = __ldg(g_ssrc + e + 1);
        int s2 = __ldg(g_ssrc + e + 2);
        int s3 = __ldg(g_ssrc + e + 3);
        float4 v0 = *reinterpret_cast<const float4*>(feat + (size_t)s0 * DD + lane * 4);
        float4 v1 = *reinterpret_cast<const float4*>(feat + (size_t)s1 * DD + lane * 4);
        float4 v2 = *reinterpret_cast<const float4*>(feat + (size_t)s2 * DD + lane * 4);
        float4 v3 = *reinterpret_cast<const float4*>(feat + (size_t)s3 * DD + lane * 4);
        a0.x += v0.x; a0.y += v0.y; a0.z += v0.z; a0.w += v0.w;
        a1.x += v1.x; a1.y += v1.y; a1.z += v1.z; a1.w += v1.w;
        a2.x += v2.x; a2.y += v2.y; a2.z += v2.z; a2.w += v2.w;
        a3.x += v3.x; a3.y += v3.y; a3.z += v3.z; a3.w += v3.w;
    }
    for (; e < end; e++) {
        int s0 = __ldg(g_ssrc + e);
        float4 v0 = *reinterpret_cast<const float4*>(feat + (size_t)s0 * DD + lane * 4);
        a0.x += v0.x; a0.y += v0.y; a0.z += v0.z; a0.w += v0.w;
    }
    float inv = g_inv[w];
    float4 r;
    r.x = (a0.x + a1.x + a2.x + a3.x) * inv;
    r.y = (a0.y + a1.y + a2.y + a3.y) * inv;
    r.z = (a0.z + a1.z + a2.z + a3.z) * inv;
    r.w = (a0.w + a1.w + a2.w + a3.w) * inv;
    *reinterpret_cast<float4*>(agg + (size_t)w * DD + lane * 4) = r;
}

// ---------------- fused SAGE layer: [128 nodes x 128 out], K=256, f32x2 ------
#define SB_PAD 132
__global__ __launch_bounds__(256, 2) void k_sage(
    const float* __restrict__ X, const float* __restrict__ Wself,
    const float* __restrict__ Wneigh, const float* __restrict__ bias,
    const float* __restrict__ gamma, const float* __restrict__ beta,
    const float* __restrict__ rm, const float* __restrict__ rv,
    float* __restrict__ OUT) {
    __shared__ __align__(16) float As[16 * SB_PAD];
    __shared__ __align__(16) float Ws[16 * 128];

    int t = threadIdx.x;
    int tj = t & 15;
    int tn = t >> 4;
    int base = blockIdx.x * 128;

    ull acc[8][4];
#pragma unroll
    for (int i = 0; i < 8; i++)
#pragma unroll
        for (int p = 0; p < 4; p++) acc[i][p] = 0ULL;

    int kkA = t & 15, n0 = t >> 4;
    int jW = t & 127, kk0 = t >> 7;

    for (int kb = 0; kb < 256; kb += 16) {
        const bool selfPart = (kb < 128);
        const int koff = selfPart ? kb : kb - 128;
        const float* SRC = selfPart ? X : g_agg;
        const float* WSRC = selfPart ? Wself : Wneigh;
#pragma unroll
        for (int i = 0; i < 8; i++) {
            int n = n0 + 16 * i;
            int row = base + n;
            float v = 0.f;
            if (row < NN) v = __ldg(SRC + (size_t)row * DD + koff + kkA);
            As[kkA * SB_PAD + n] = v;
        }
#pragma unroll
        for (int i = 0; i < 8; i++) {
            int kk = kk0 + 2 * i;
            Ws[kk * 128 + jW] = __ldg(WSRC + (size_t)(koff + kk) * DD + jW);
        }
        __syncthreads();
#pragma unroll
        for (int kk = 0; kk < 16; kk++) {
            const float* wrow = Ws + kk * 128 + tj * 8;
            ull w01 = *reinterpret_cast<const ull*>(wrow + 0);
            ull w23 = *reinterpret_cast<const ull*>(wrow + 2);
            ull w45 = *reinterpret_cast<const ull*>(wrow + 4);
            ull w67 = *reinterpret_cast<const ull*>(wrow + 6);
            float4 a0 = *reinterpret_cast<float4*>(As + kk * SB_PAD + tn * 8);
            float4 a1 = *reinterpret_cast<float4*>(As + kk * SB_PAD + tn * 8 + 4);
            float av[8] = {a0.x, a0.y, a0.z, a0.w, a1.x, a1.y, a1.z, a1.w};
#pragma unroll
            for (int i = 0; i < 8; i++) {
                ull ap = pack2(av[i], av[i]);
                ffma2(acc[i][0], ap, w01);
                ffma2(acc[i][1], ap, w23);
                ffma2(acc[i][2], ap, w45);
                ffma2(acc[i][3], ap, w67);
            }
        }
        __syncthreads();
    }

    int j = tj * 8;
    float sj[8], shj[8];
#pragma unroll
    for (int q = 0; q < 8; q++) {
        float gq = __ldg(gamma + j + q);
        float rq = __ldg(rv + j + q);
        float bq = __ldg(bias + j + q);
        float mq = __ldg(rm + j + q);
        float eq = __ldg(beta + j + q);
        sj[q] = gq * rsqrtf(rq + 1e-5f);
        shj[q] = sj[q] * (bq - mq) + eq;
    }
#pragma unroll
    for (int i = 0; i < 8; i++) {
        int row = base + tn * 8 + i;
        if (row >= NN) continue;
        float o[8];
#pragma unroll
        for (int p = 0; p < 4; p++) {
            float2 v = unpack2(acc[i][p]);
            o[2 * p] = v.x;
            o[2 * p + 1] = v.y;
        }
        float4 r0, r1;
#pragma unroll
        for (int q = 0; q < 8; q++) {
            float v = sj[q] * o[q] + shj[q];
            v = v > 0.f ? v : 0.01f * v;
            if (q < 4) (&r0.x)[q] = v; else (&r1.x)[q - 4] = v;
        }
        *reinterpret_cast<float4*>(OUT + (size_t)row * DD + j) = r0;
        *reinterpret_cast<float4*>(OUT + (size_t)row * DD + j + 4) = r1;
    }
}

// ---------------- PQ GEMM: PQ = h1 @ [W0a | W0b], +mb0 on P half -------------
// mw0 is [257][64] row-major. PQ[n][j<64] = sum_k h1[n][k]*mw0[k][j] + mb0[j]
//                             PQ[n][j>=64] = sum_k h1[n][k]*mw0[128+k][j-64]
__global__ __launch_bounds__(256, 2) void k_pq(
    const float* __restrict__ H, const float* __restrict__ mw0,
    const float* __restrict__ mb0, float* __restrict__ OUT) {
    __shared__ __align__(16) float As[16 * SB_PAD];
    __shared__ __align__(16) float Ws[16 * 128];

    int t = threadIdx.x;
    int tj = t & 15;
    int tn = t >> 4;
    int base = blockIdx.x * 128;

    ull acc[8][4];
#pragma unroll
    for (int i = 0; i < 8; i++)
#pragma unroll
        for (int p = 0; p < 4; p++) acc[i][p] = 0ULL;

    int kkA = t & 15, n0 = t >> 4;
    int jW = t & 127, kk0 = t >> 7;

    for (int kb = 0; kb < 128; kb += 16) {
#pragma unroll
        for (int i = 0; i < 8; i++) {
            int n = n0 + 16 * i;
            int row = base + n;
            float v = 0.f;
            if (row < NN) v = __ldg(H + (size_t)row * DD + kb + kkA);
            As[kkA * SB_PAD + n] = v;
        }
#pragma unroll
        for (int i = 0; i < 8; i++) {
            int kk = kk0 + 2 * i;
            int k = kb + kk;
            float wv = (jW < 64) ? __ldg(mw0 + (size_t)k * 64 + jW)
                                 : __ldg(mw0 + (size_t)(128 + k) * 64 + (jW - 64));
            Ws[kk * 128 + jW] = wv;
        }
        __syncthreads();
#pragma unroll
        for (int kk = 0; kk < 16; kk++) {
            const float* wrow = Ws + kk * 128 + tj * 8;
            ull w01 = *reinterpret_cast<const ull*>(wrow + 0);
            ull w23 = *reinterpret_cast<const ull*>(wrow + 2);
            ull w45 = *reinterpret_cast<const ull*>(wrow + 4);
            ull w67 = *reinterpret_cast<const ull*>(wrow + 6);
            float4 a0 = *reinterpret_cast<float4*>(As + kk * SB_PAD + tn * 8);
            float4 a1 = *reinterpret_cast<float4*>(As + kk * SB_PAD + tn * 8 + 4);
            float av[8] = {a0.x, a0.y, a0.z, a0.w, a1.x, a1.y, a1.z, a1.w};
#pragma unroll
            for (int i = 0; i < 8; i++) {
                ull ap = pack2(av[i], av[i]);
                ffma2(acc[i][0], ap, w01);
                ffma2(acc[i][1], ap, w23);
                ffma2(acc[i][2], ap, w45);
                ffma2(acc[i][3], ap, w67);
            }
        }
        __syncthreads();
    }

    int j = tj * 8;
    float bj[8];
#pragma unroll
    for (int q = 0; q < 8; q++)
        bj[q] = (j + q < 64) ? __ldg(mb0 + j + q) : 0.f;
#pragma unroll
    for (int i = 0; i < 8; i++) {
        int row = base + tn * 8 + i;
        if (row >= NN) continue;
        float4 r0, r1;
#pragma unroll
        for (int p = 0; p < 4; p++) {
            float2 v = unpack2(acc[i][p]);
            float a = v.x + bj[2 * p];
            float b = v.y + bj[2 * p + 1];
            if (p < 2) { (&r0.x)[2 * p] = a; (&r0.x)[2 * p + 1] = b; }
            else       { (&r1.x)[2 * (p - 2)] = a; (&r1.x)[2 * (p - 2) + 1] = b; }
        }
        *reinterpret_cast<float4*>(OUT + (size_t)row * DD + j) = r0;
        *reinterpret_cast<float4*>(OUT + (size_t)row * DD + j + 4) = r1;
    }
}

// ---------------- candidate kernel: gather PQ, layers 1-2, f32x2 -------------
__global__ __launch_bounds__(128) void k_cand(
    const int* __restrict__ cu, const int* __restrict__ cv,
    const float* __restrict__ cf, const float* __restrict__ mw0,
    const float* __restrict__ mw1, const float* __restrict__ mb1,
    const float* __restrict__ mw2, const float* __restrict__ mb2) {
    __shared__ float Z0[64 * 68];   // [k][c]
    __shared__ float Z2[64 * 68];
    __shared__ float W256[64];

    int t = threadIdx.x;
    int cbase = blockIdx.x * 64;
    int w = t >> 5, lane = t & 31;

    if (t < 64) W256[t] = __ldg(mw0 + 256 * 64 + t);
    __syncthreads();

    // layer 0: z0 = lrelu(P[u] + Q[v] + cf*w256)  (mb0 already folded into P)
    for (int ci = 0; ci < 16; ci++) {
        int c = w * 16 + ci;
        int cg = cbase + c;
        int cgc = cg < CC ? cg : 0;
        int u = __ldg(cu + cgc);
        int v = __ldg(cv + cgc);
        float cfv = __ldg(cf + cgc);
        float2 p = *reinterpret_cast<const float2*>(g_pq + (size_t)u * DD + lane * 2);
        float2 q = *reinterpret_cast<const float2*>(g_pq + (size_t)v * DD + 64 + lane * 2);
        float z0 = p.x + q.x + cfv * W256[lane * 2];
        float z1 = p.y + q.y + cfv * W256[lane * 2 + 1];
        z0 = z0 > 0.f ? z0 : 0.01f * z0;
        z1 = z1 > 0.f ? z1 : 0.01f * z1;
        Z0[(lane * 2) * 68 + c] = z0;
        Z0[(lane * 2 + 1) * 68 + c] = z1;
    }
    __syncthreads();

    int tj = t & 15;   // j = tj*4 + jj
    int tc = t >> 4;   // c = tc*8 + i
    ull acc[8][2];
#pragma unroll
    for (int i = 0; i < 8; i++) { acc[i][0] = 0ULL; acc[i][1] = 0ULL; }

    // layer 1: K = 64
    for (int k = 0; k < 64; k++) {
        float4 wv = __ldg(reinterpret_cast<const float4*>(mw1 + k * 64 + tj * 4));
        ull w01 = pack2(wv.x, wv.y);
        ull w23 = pack2(wv.z, wv.w);
        float4 a0 = *reinterpret_cast<float4*>(Z0 + k * 68 + tc * 8);
        float4 a1 = *reinterpret_cast<float4*>(Z0 + k * 68 + tc * 8 + 4);
        float av[8] = {a0.x, a0.y, a0.z, a0.w, a1.x, a1.y, a1.z, a1.w};
#pragma unroll
        for (int i = 0; i < 8; i++) {
            ull ap = pack2(av[i], av[i]);
            ffma2(acc[i][0], ap, w01);
            ffma2(acc[i][1], ap, w23);
        }
    }
    {
        float4 bv = __ldg(reinterpret_cast<const float4*>(mb1 + tj * 4));
#pragma unroll
        for (int i = 0; i < 8; i++) {
            float2 p0 = unpack2(acc[i][0]);
            float2 p1 = unpack2(acc[i][1]);
            float vx = p0.x + bv.x; vx = vx > 0.f ? vx : 0.01f * vx;
            float vy = p0.y + bv.y; vy = vy > 0.f ? vy : 0.01f * vy;
            float vz = p1.x + bv.z; vz = vz > 0.f ? vz : 0.01f * vz;
            float vw = p1.y + bv.w; vw = vw > 0.f ? vw : 0.01f * vw;
            int c = tc * 8 + i;
            Z2[(tj * 4 + 0) * 68 + c] = vx;
            Z2[(tj * 4 + 1) * 68 + c] = vy;
            Z2[(tj * 4 + 2) * 68 + c] = vz;
            Z2[(tj * 4 + 3) * 68 + c] = vw;
        }
    }
    __syncthreads();

    // layer 2: y[c] = z2 . mw2 + mb2
    if (t < 64) {
        int c = t;
        float a = __ldg(mb2);
#pragma unroll 8
        for (int j = 0; j < 64; j++) a += Z2[j * 68 + c] * __ldg(mw2 + j);
        int cg = cbase + c;
        if (cg < CC) g_y[cg] = a;
    }
}

// ---------------- softmax over C ---------------------------------------------
__global__ void k_max_part() {
    __shared__ float s[256];
    int t = threadIdx.x;
    float m = -1e30f;
    for (int i = blockIdx.x * 256 + t; i < CC; i += 256 * 256) m = fmaxf(m, g_y[i]);
    s[t] = m;
    __syncthreads();
    for (int o = 128; o > 0; o >>= 1) {
        if (t < o) s[t] = fmaxf(s[t], s[t + o]);
        __syncthreads();
    }
    if (t == 0) g_pmax[blockIdx.x] = s[0];
}

__global__ void k_sumexp() {
    __shared__ float s[1024];
    int t = threadIdx.x;
    s[t] = (t < 256) ? g_pmax[t] : -1e30f;
    __syncthreads();
    for (int o = 512; o > 0; o >>= 1) {
        if (t < o) s[t] = fmaxf(s[t], s[t + o]);
        __syncthreads();
    }
    float M = s[0];
    __syncthreads();
    float sum = 0.f;
    for (int i = t; i < CC; i += 1024) sum += expf(g_y[i] - M);
    s[t] = sum;
    __syncthreads();
    for (int o = 512; o > 0; o >>= 1) {
        if (t < o) s[t] += s[t + o];
        __syncthreads();
    }
    if (t == 0) { g_MS[0] = M; g_MS[1] = s[0]; }
}

__global__ void k_writeout(float* __restrict__ out, int out_size) {
    int i = blockIdx.x * blockDim.x + threadIdx.x;
    if (i >= CC) return;
    float y = g_y[i];
    if (out_size >= CC) out[i] = y;
    if (out_size >= 2 * CC) out[CC + i] = expf(y - g_MS[0]) / g_MS[1];
}

// ---------------- launch -----------------------------------------------------
extern "C" void kernel_launch(void* const* d_in, const int* in_sizes, int n_in,
                              void* d_out, int out_size) {
    const float* x   = (const float*)d_in[0];
    const int*   src = (const int*)d_in[1];
    const int*   dst = (const int*)d_in[2];
    const int*   cu  = (const int*)d_in[3];
    const int*   cv  = (const int*)d_in[4];
    const float* cf  = (const float*)d_in[5];
    const float* ws0 = (const float*)d_in[6];
    const float* wn0 = (const float*)d_in[7];
    const float* b0  = (const float*)d_in[8];
    const float* g0  = (const float*)d_in[9];
    const float* be0 = (const float*)d_in[10];
    const float* rm0 = (const float*)d_in[11];
    const float* rv0 = (const float*)d_in[12];
    const float* ws1 = (const float*)d_in[13];
    const float* wn1 = (const float*)d_in[14];
    const float* b1  = (const float*)d_in[15];
    const float* g1  = (const float*)d_in[16];
    const float* be1 = (const float*)d_in[17];
    const float* rm1 = (const float*)d_in[18];
    const float* rv1 = (const float*)d_in[19];
    const float* mw0 = (const float*)d_in[20];
    const float* mb0 = (const float*)d_in[21];
    const float* mw1 = (const float*)d_in[22];
    const float* mb1 = (const float*)d_in[23];
    const float* mw2 = (const float*)d_in[24];
    const float* mb2 = (const float*)d_in[25];
    float* out = (float*)d_out;

    void *p_agg = nullptr, *p_h0 = nullptr, *p_h1 = nullptr, *p_pq = nullptr;
    cudaGetSymbolAddress(&p_agg, g_agg);
    cudaGetSymbolAddress(&p_h0, g_h0);
    cudaGetSymbolAddress(&p_h1, g_h1);
    cudaGetSymbolAddress(&p_pq, g_pq);

    const int sageBlocks = (NN + 127) / 128;
    const int candBlocks = (CC + 63) / 64;
    const int aggBlocks = (NN * 32 + 255) / 256;

    // ---- CSR build ----
    k_zero_cnt<<<(NN + 255) / 256, 256>>>();
    k_hist<<<(EE + 255) / 256, 256>>>(dst);
    k_scan<<<1, 1024>>>();
    k_fill<<<(EE + 255) / 256, 256>>>(src, dst);

    // ---- layer 0 ----
    k_agg<<<aggBlocks, 256>>>(x, (float*)p_agg);
    k_sage<<<sageBlocks, 256>>>(x, ws0, wn0, b0, g0, be0, rm0, rv0, (float*)p_h0);
    // ---- layer 1 ----
    k_agg<<<aggBlocks, 256>>>((const float*)p_h0, (float*)p_agg);
    k_sage<<<sageBlocks, 256>>>((const float*)p_h0, ws1, wn1, b1, g1, be1, rm1, rv1,
                                (float*)p_h1);
    // ---- candidate path ----
    k_pq<<<sageBlocks, 256>>>((const float*)p_h1, mw0, mb0, (float*)p_pq);
    k_cand<<<candBlocks, 128>>>(cu, cv, cf, mw0, mw1, mb1, mw2, mb2);
    // ---- softmax + output ----
    k_max_part<<<256, 256>>>();
    k_sumexp<<<1, 1024>>>();
    k_writeout<<<(CC + 255) / 256, 256>>>(out, out_size);
}